// round 14
// baseline (speedup 1.0000x reference)
#include <cuda_runtime.h>
#include <cuda_fp16.h>
#include <cstdint>

#define D 128
#define MAXN 50048
#define MAXE 800000

// ---------------- scratch (device globals: no allocation allowed) ----------
__device__ __half g_xwA[(size_t)MAXN * D];  // xw ping
__device__ __half g_xwB[(size_t)MAXN * D];  // xw pong
__device__ float  g_dinv[MAXN];
__device__ int    g_count[MAXN];
__device__ int    g_off[MAXN + 1];
__device__ int    g_cursor[MAXN];
__device__ uint2  g_csr[MAXE];              // {src, w bits} packed per edge
__device__ int    g_bsum[256];
__device__ uint2  g_wfh[3][4096];           // prebuilt fp16 W fragments

// ---------------- helpers ---------------------------------------------------
__device__ __forceinline__ int probe_is64(const void* ei) {
    const uint4* p = (const uint4*)ei;
    uint4 a = p[0], b = p[1], c = p[2], d4 = p[3];
    unsigned int odd = a.y | a.w | b.y | b.w | c.y | c.w | d4.y | d4.w;
    return odd == 0u;
}
__device__ __forceinline__ int load_idx(const void* ei, long long i, int is64) {
    if (is64) return (int)((const long long*)ei)[i];
    return ((const int*)ei)[i];
}
__device__ __forceinline__ uint32_t pack_f16(float x, float y) {
    __half2 p = __floats2half2_rn(x, y);
    return *(uint32_t*)&p;
}

// ---------------- init: zero counts + build fp16 W fragments ----------------
__global__ void k_init(const float* __restrict__ W1,
                       const float* __restrict__ W2,
                       const float* __restrict__ W3, int n) {
    if (blockIdx.x < 48) {
        int gid = blockIdx.x * 256 + threadIdx.x;     // 0..12287
        int m   = gid >> 12;
        int idx = gid & 4095;
        const float* W = (m == 0) ? W1 : (m == 1) ? W2 : W3;
        int ln = idx & 31;
        int nt = (idx >> 5) & 15;
        int ks = idx >> 9;
        int gg = ln >> 2, tt = ln & 3;
        int k0 = ks * 16 + tt * 2;
        int nn = nt * 8 + gg;
        float w00 = W[(size_t)k0 * D + nn];
        float w01 = W[(size_t)(k0 + 1) * D + nn];
        float w10 = W[(size_t)(k0 + 8) * D + nn];
        float w11 = W[(size_t)(k0 + 9) * D + nn];
        uint2 v;
        v.x = pack_f16(w00, w01);
        v.y = pack_f16(w10, w11);
        g_wfh[m][idx] = v;
    } else {
        int i = (blockIdx.x - 48) * 256 + threadIdx.x;
        if (i < n) g_count[i] = 0;
    }
}

__global__ void k_count(const void* __restrict__ ei, int e) {
    int is64 = probe_is64(ei);
    int idx = blockIdx.x * blockDim.x + threadIdx.x;
    if (idx >= e) return;
    int d = load_idx(ei, (long long)e + idx, is64);
    atomicAdd(&g_count[d], 1);
}

__global__ void k_scan_p1(int n) {
    int blk = blockIdx.x, t = threadIdx.x;
    int base = blk * 1024 + t * 4;
    int s = 0;
#pragma unroll
    for (int j = 0; j < 4; j++) {
        int i = base + j;
        if (i < n) s += g_count[i];
    }
    __shared__ int sh[256];
    sh[t] = s;
    __syncthreads();
#pragma unroll
    for (int d = 128; d; d >>= 1) {
        if (t < d) sh[t] += sh[t + d];
        __syncthreads();
    }
    if (t == 0) g_bsum[blk] = sh[0];
}

__global__ void k_scan_p23(int n, int nblocks) {
    int blk = blockIdx.x, t = threadIdx.x;
    __shared__ int sh2[256];
    int v2 = (t < nblocks) ? g_bsum[t] : 0;
    sh2[t] = v2;
    __syncthreads();
    for (int d = 1; d < 256; d <<= 1) {
        int a = (t >= d) ? sh2[t - d] : 0;
        __syncthreads();
        sh2[t] += a;
        __syncthreads();
    }
    int bbase = (blk == 0) ? 0 : sh2[blk - 1];
    if (blk == 0 && t == 255) g_off[n] = sh2[255];
    __syncthreads();

    int base = blk * 1024 + t * 4;
    int c[4];
    int s = 0;
#pragma unroll
    for (int j = 0; j < 4; j++) {
        int i = base + j;
        c[j] = (i < n) ? g_count[i] : 0;
        s += c[j];
    }
    __shared__ int sh[256];
    sh[t] = s;
    __syncthreads();
    for (int d = 1; d < 256; d <<= 1) {
        int a = (t >= d) ? sh[t - d] : 0;
        __syncthreads();
        sh[t] += a;
        __syncthreads();
    }
    int tb = bbase + sh[t] - s;
#pragma unroll
    for (int j = 0; j < 4; j++) {
        int i = base + j;
        if (i < n) {
            g_off[i]    = tb;
            g_cursor[i] = tb;
            g_dinv[i]   = rsqrtf((float)c[j] + 1.0f);
            tb += c[j];
        }
    }
}

__global__ void k_fill(const void* __restrict__ ei, int e) {
    int is64 = probe_is64(ei);
    int idx = blockIdx.x * blockDim.x + threadIdx.x;
    if (idx >= e) return;
    int s = load_idx(ei, idx, is64);
    int d = load_idx(ei, (long long)e + idx, is64);
    int pos = atomicAdd(&g_cursor[d], 1);
    float w = g_dinv[s] * g_dinv[d];
    uint2 p;
    p.x = (unsigned)s;
    p.y = __float_as_uint(w);
    g_csr[pos] = p;
}

// ---------------- MMA helper -----------------------------------------------
__device__ __forceinline__ void mma_f16(float c[4], const uint32_t a[4],
                                        uint32_t b0, uint32_t b1) {
    asm volatile(
        "mma.sync.aligned.m16n8k16.row.col.f32.f16.f16.f32 "
        "{%0,%1,%2,%3}, {%4,%5,%6,%7}, {%8,%9}, {%0,%1,%2,%3};"
        : "+f"(c[0]), "+f"(c[1]), "+f"(c[2]), "+f"(c[3])
        : "r"(a[0]), "r"(a[1]), "r"(a[2]), "r"(a[3]), "r"(b0), "r"(b1));
}

// warp-level aggregate of node d: acc = self + sum_j w_j * src[s_j], +bias,relu
__device__ __forceinline__ float4 agg_node(const __half* __restrict__ src,
                                           int d, int lane, float4 b4) {
    float di = g_dinv[d];
    float self = di * di;
    uint2 us = *(const uint2*)(src + (size_t)d * D + lane * 4);
    float2 s0 = __half22float2(*(const __half2*)&us.x);
    float2 s1 = __half22float2(*(const __half2*)&us.y);
    float4 acc = make_float4(s0.x * self, s0.y * self, s1.x * self, s1.y * self);

    int j0 = g_off[d], j1 = g_off[d + 1];
    int j = j0;
    for (; j + 1 < j1; j += 2) {           // 2x unroll -> MLP 2
        uint2 cp0 = g_csr[j];
        uint2 cp1 = g_csr[j + 1];
        uint2 u0 = *(const uint2*)(src + (size_t)(int)cp0.x * D + lane * 4);
        uint2 u1 = *(const uint2*)(src + (size_t)(int)cp1.x * D + lane * 4);
        float w0 = __uint_as_float(cp0.y);
        float w1 = __uint_as_float(cp1.y);
        float2 a0 = __half22float2(*(const __half2*)&u0.x);
        float2 a1 = __half22float2(*(const __half2*)&u0.y);
        float2 b0 = __half22float2(*(const __half2*)&u1.x);
        float2 b1 = __half22float2(*(const __half2*)&u1.y);
        acc.x += w0 * a0.x + w1 * b0.x;
        acc.y += w0 * a0.y + w1 * b0.y;
        acc.z += w0 * a1.x + w1 * b1.x;
        acc.w += w0 * a1.y + w1 * b1.y;
    }
    if (j < j1) {
        uint2 cp = g_csr[j];
        uint2 u = *(const uint2*)(src + (size_t)(int)cp.x * D + lane * 4);
        float w = __uint_as_float(cp.y);
        float2 f0 = __half22float2(*(const __half2*)&u.x);
        float2 f1 = __half22float2(*(const __half2*)&u.y);
        acc.x += w * f0.x; acc.y += w * f0.y;
        acc.z += w * f1.x; acc.w += w * f1.y;
    }
    acc.x = fmaxf(acc.x + b4.x, 0.f);
    acc.y = fmaxf(acc.y + b4.y, 0.f);
    acc.z = fmaxf(acc.z + b4.z, 0.f);
    acc.w = fmaxf(acc.w + b4.w, 0.f);
    return acc;
}

// ---------------- layer-1 GEMM: dst = x(fp32) @ W[0] -----------------------
extern __shared__ char s_raw[];

__global__ void __launch_bounds__(256, 3)
k_gemm1(const float* __restrict__ x, __half* __restrict__ dst, int n) {
    uint2* s_wf = (uint2*)s_raw;   // 32KB
    int tid  = threadIdx.x;
    int warp = tid >> 5;
    int lane = tid & 31;
    int g    = lane >> 2;
    int tig  = lane & 3;

    {
        const uint4* src = (const uint4*)g_wfh[0];
        uint4* dstc = (uint4*)s_wf;
#pragma unroll
        for (int v = 0; v < 8; v++) dstc[v * 256 + tid] = src[v * 256 + tid];
    }

    int rbase = blockIdx.x * 128 + warp * 16;
    int r0 = rbase + g;
    int r1 = r0 + 8;
    int r0c = r0 < n ? r0 : n - 1;
    int r1c = r1 < n ? r1 : n - 1;
    const float* p0 = x + (size_t)r0c * D;
    const float* p1 = x + (size_t)r1c * D;

    uint32_t a[8][4];
#pragma unroll
    for (int ks = 0; ks < 8; ks++) {
        int k0 = ks * 16 + tig * 2;
        float2 x0 = *(const float2*)(p0 + k0);
        float2 x1 = *(const float2*)(p1 + k0);
        float2 x2 = *(const float2*)(p0 + k0 + 8);
        float2 x3 = *(const float2*)(p1 + k0 + 8);
        a[ks][0] = pack_f16(x0.x, x0.y);
        a[ks][1] = pack_f16(x1.x, x1.y);
        a[ks][2] = pack_f16(x2.x, x2.y);
        a[ks][3] = pack_f16(x3.x, x3.y);
    }
    __syncthreads();

#pragma unroll 2
    for (int nt = 0; nt < 16; nt++) {
        float c[4] = {0.f, 0.f, 0.f, 0.f};
#pragma unroll
        for (int ks = 0; ks < 8; ks++) {
            uint2 b = s_wf[(ks * 16 + nt) * 32 + lane];
            mma_f16(c, a[ks], b.x, b.y);
        }
        int col = nt * 8 + tig * 2;
        if (r0 < n)
            *(__half2*)(dst + (size_t)r0 * D + col) = __floats2half2_rn(c[0], c[1]);
        if (r1 < n)
            *(__half2*)(dst + (size_t)r1 * D + col) = __floats2half2_rn(c[2], c[3]);
    }
}

// ---------------- fused aggregate + GEMM ------------------------------------
// smem: [0,32KB) W frags; [32KB, +34816) h tile (128 rows x 68 words).
__global__ void __launch_bounds__(256, 3)
k_agg_gemm(const __half* __restrict__ src, __half* __restrict__ dst,
           const float* __restrict__ bias, int wsel, int n) {
    uint2*    s_wf = (uint2*)s_raw;
    uint32_t* s_h  = (uint32_t*)(s_raw + 32768);
    int tid  = threadIdx.x;
    int warp = tid >> 5;
    int lane = tid & 31;
    int g    = lane >> 2;
    int tig  = lane & 3;

    // W fragment copy (no sync needed until phase 2)
    {
        const uint4* wsrc = (const uint4*)g_wfh[wsel];
        uint4* wdst = (uint4*)s_wf;
#pragma unroll
        for (int v = 0; v < 8; v++) wdst[v * 256 + tid] = wsrc[v * 256 + tid];
    }

    // phase 1: aggregate 16 nodes per warp into the smem h tile
    int rbase = blockIdx.x * 128;
    float4 b4 = *(const float4*)(bias + lane * 4);
    for (int i = 0; i < 16; i++) {
        int lr = warp * 16 + i;
        int d  = rbase + lr;
        uint32_t* hp = s_h + lr * 68 + lane * 2;
        if (d < n) {
            float4 acc = agg_node(src, d, lane, b4);
            uint2 r;
            r.x = pack_f16(acc.x, acc.y);
            r.y = pack_f16(acc.z, acc.w);
            *(uint2*)hp = r;
        } else {
            uint2 z = make_uint2(0u, 0u);
            *(uint2*)hp = z;
        }
    }
    __syncthreads();

    // phase 2: GEMM from the smem h tile (stride-68 rows: conflict-free)
    uint32_t a[8][4];
    {
        int ra = warp * 16 + g;
        int rb = ra + 8;
#pragma unroll
        for (int ks = 0; ks < 8; ks++) {
            int c0 = ks * 8 + tig;
            a[ks][0] = s_h[ra * 68 + c0];
            a[ks][1] = s_h[rb * 68 + c0];
            a[ks][2] = s_h[ra * 68 + c0 + 4];
            a[ks][3] = s_h[rb * 68 + c0 + 4];
        }
    }

    int r0 = rbase + warp * 16 + g;
    int r1 = r0 + 8;
#pragma unroll 2
    for (int nt = 0; nt < 16; nt++) {
        float c[4] = {0.f, 0.f, 0.f, 0.f};
#pragma unroll
        for (int ks = 0; ks < 8; ks++) {
            uint2 b = s_wf[(ks * 16 + nt) * 32 + lane];
            mma_f16(c, a[ks], b.x, b.y);
        }
        int col = nt * 8 + tig * 2;
        if (r0 < n)
            *(__half2*)(dst + (size_t)r0 * D + col) = __floats2half2_rn(c[0], c[1]);
        if (r1 < n)
            *(__half2*)(dst + (size_t)r1 * D + col) = __floats2half2_rn(c[2], c[3]);
    }
}

// ---------------- final aggregate + fc head ---------------------------------
__global__ void k_aggfc(const __half* __restrict__ src,
                        const float* __restrict__ bias, int n,
                        const float* __restrict__ Wfc,
                        const float* __restrict__ bfc,
                        float* __restrict__ out) {
    int warp = (blockIdx.x * blockDim.x + threadIdx.x) >> 5;
    if (warp >= n) return;
    int lane = threadIdx.x & 31;
    float4 b4 = *(const float4*)(bias + lane * 4);
    float4 acc = agg_node(src, warp, lane, b4);
    float4 wf = *(const float4*)(Wfc + lane * 4);
    float s = acc.x * wf.x + acc.y * wf.y + acc.z * wf.z + acc.w * wf.w;
#pragma unroll
    for (int o = 16; o; o >>= 1) s += __shfl_xor_sync(0xFFFFFFFFu, s, o);
    if (lane == 0) out[warp] = s + bfc[0];
}

// ---------------- launch -----------------------------------------------------
extern "C" void kernel_launch(void* const* d_in, const int* in_sizes, int n_in,
                              void* d_out, int out_size) {
    const float* x   = (const float*)d_in[0];
    const void*  ei  = d_in[1];
    const float* W1  = (const float*)d_in[2];
    const float* b1  = (const float*)d_in[3];
    const float* W2  = (const float*)d_in[4];
    const float* b2  = (const float*)d_in[5];
    const float* W3  = (const float*)d_in[6];
    const float* b3  = (const float*)d_in[7];
    const float* Wfc = (const float*)d_in[8];
    const float* bfc = (const float*)d_in[9];
    float* out = (float*)d_out;

    int n = in_sizes[0] / D;   // 50000
    int e = in_sizes[1] / 2;   // 800000

    int nb  = (n + 255) / 256;
    int eb  = (e + 255) / 256;
    int sb  = (n + 1023) / 1024;
    int gemm_grid = (n + 127) / 128;
    int warp_grid = (n + 7) / 8;
    int fused_smem = 32768 + 34816;

    static cudaStream_t s2 = nullptr;
    static cudaEvent_t ev_fork = nullptr, ev_join = nullptr;
    static __half *xwA = nullptr, *xwB = nullptr;
    if (!s2) {
        cudaStreamCreateWithFlags(&s2, cudaStreamNonBlocking);
        cudaEventCreateWithFlags(&ev_fork, cudaEventDisableTiming);
        cudaEventCreateWithFlags(&ev_join, cudaEventDisableTiming);
        cudaFuncSetAttribute(k_gemm1,
                             cudaFuncAttributeMaxDynamicSharedMemorySize, 32768);
        cudaFuncSetAttribute(k_agg_gemm,
                             cudaFuncAttributeMaxDynamicSharedMemorySize, fused_smem);
        cudaGetSymbolAddress((void**)&xwA, g_xwA);
        cudaGetSymbolAddress((void**)&xwB, g_xwB);
    }

    k_init<<<48 + nb, 256>>>(W1, W2, W3, n);               // 0
    cudaEventRecord(ev_fork, 0);
    k_count<<<eb, 256>>>(ei, e);                           // 1
    k_scan_p1<<<sb, 256>>>(n);                             // 2
    cudaStreamWaitEvent(s2, ev_fork, 0);
    k_gemm1<<<gemm_grid, 256, 32768, s2>>>(x, xwA, n);     // 3 (|| count/scan/fill)
    cudaEventRecord(ev_join, s2);
    k_scan_p23<<<sb, 256>>>(n, sb);                        // 4
    k_fill<<<eb, 256>>>(ei, e);                            // 5
    cudaStreamWaitEvent(0, ev_join, 0);                    // join

    k_agg_gemm<<<gemm_grid, 256, fused_smem>>>(xwA, xwB, b1, 1, n);  // 6
    k_agg_gemm<<<gemm_grid, 256, fused_smem>>>(xwB, xwA, b2, 2, n);  // 7
    k_aggfc<<<warp_grid, 256>>>(xwA, b3, n, Wfc, bfc, out);          // 8
}